// round 1
// baseline (speedup 1.0000x reference)
#include <cuda_runtime.h>

#define BB 4
#define CC 17
#define TT 75000
#define HH 32
#define KK 8
#define NTHREADS 256
#define TILE 4096
#define NTILE 19          // ceil(75000/4096)
#define NCOMBO_TILE 18    // di 0..8, diff 0..1
#define MAXPART 32

// Deterministic partial accumulation scratch: [combo 28][b 4][h 32][part 32][16]
__device__ float g_partial[28][4][32][MAXPART][16];

__device__ __forceinline__ float gsum(const float* __restrict__ Xb,
                                      const int off[8], int t, int diff) {
    float s = 0.f;
#pragma unroll
    for (int i = 0; i < 8; i++) {
        const float* p = Xb + off[i] + t;
        float x = __ldg(p);
        if (diff) x = __ldg(p + 1) - x;
        s += x;
    }
    return s;
}

// --- shared helpers: per-position conv + reduce into register accumulators ---
__device__ __forceinline__ void conv_reduce(const float gv[9], const float w[8][9],
                                            float am[8], float an[8]) {
    float z[8];
#pragma unroll
    for (int k = 0; k < 8; k++) {
        float s = gv[0] * w[k][0];
#pragma unroll
        for (int j = 1; j < 9; j++) s = fmaf(gv[j], w[k][j], s);
        z[k] = s;
    }
    float mx = z[0]; int im = 0;
    float mn = z[0]; int imn = 0;
#pragma unroll
    for (int k = 1; k < 8; k++) {
        if (z[k] > mx) { mx = z[k]; im = k; }
        if (z[k] < mn) { mn = z[k]; imn = k; }
    }
#pragma unroll
    for (int k = 0; k < 8; k++) {
        am[k] += (im == k) ? mx : 0.f;
        an[k] += (imn == k) ? 1.f : 0.f;
    }
}

__device__ __forceinline__ void block_write_partial(float am[8], float an[8],
                                                    int ci, int b, int h, int blk) {
    __shared__ float sw[8][16];
    int tid = threadIdx.x;
    int lane = tid & 31, warp = tid >> 5;
#pragma unroll
    for (int o = 0; o < 16; o++) {
        float v = (o < 8) ? am[o] : an[o - 8];
        v += __shfl_down_sync(0xffffffffu, v, 16);
        v += __shfl_down_sync(0xffffffffu, v, 8);
        v += __shfl_down_sync(0xffffffffu, v, 4);
        v += __shfl_down_sync(0xffffffffu, v, 2);
        v += __shfl_down_sync(0xffffffffu, v, 1);
        if (lane == 0) sw[warp][o] = v;
    }
    __syncthreads();
    if (tid < 16) {
        float s = 0.f;
#pragma unroll
        for (int wN = 0; wN < 8; wN++) s += sw[wN][tid];
        g_partial[ci][b][h][blk][tid] = s;
    }
}

// ============================================================================
// Path A: small dilation (d = 1..256), shared-memory g tile with halo.
// grid.x = 18 * 4 * 32 * 19, block = 256
// ============================================================================
__global__ void __launch_bounds__(256, 2)
tile_kernel(const float* __restrict__ X, const float* __restrict__ W,
            const int* __restrict__ idx) {
    int bx = blockIdx.x;
    int tile = bx % NTILE;
    int h = (bx / NTILE) % HH;
    int b = (bx / (NTILE * HH)) % BB;
    int ci = bx / (NTILE * HH * BB);   // 0..17 == di*2+diff
    int di = ci >> 1, diff = ci & 1;
    int d = 1 << di;
    int Te = TT - diff;                // valid length (output length == input length)
    int t0 = tile * TILE;
    int tid = threadIdx.x;

    extern __shared__ float g_sh[];    // TILE + 8*d floats (max 6144)

    // channel byte-offsets
    int off[8];
    {
        const int* ip = idx + (ci * HH + h) * 8;
#pragma unroll
        for (int i = 0; i < 8; i++) off[i] = ip[i] * TT;
    }
    const float* Xb = X + b * CC * TT;

    // build g tile (with halo, zero padded)
    int halo = 4 * d;
    int n = TILE + 2 * halo;
    for (int i = tid; i < n; i += NTHREADS) {
        int t = t0 - halo + i;
        float v = 0.f;
        if (t >= 0 && t < Te) v = gsum(Xb, off, t, diff);
        g_sh[i] = v;
    }

    // weights -> registers (uniform across block)
    float w[8][9];
    {
        const float* wp = W + (ci * 256 + h * 8) * 9;
#pragma unroll
        for (int k = 0; k < 8; k++)
#pragma unroll
            for (int j = 0; j < 9; j++) w[k][j] = __ldg(wp + k * 9 + j);
    }
    __syncthreads();

    float am[8] = {0, 0, 0, 0, 0, 0, 0, 0};
    float an[8] = {0, 0, 0, 0, 0, 0, 0, 0};

#pragma unroll 1
    for (int p = 0; p < TILE / NTHREADS; p++) {
        int q = tid + p * NTHREADS;
        int t = t0 + q;
        if (t < Te) {
            float gv[9];
#pragma unroll
            for (int j = 0; j < 9; j++) gv[j] = g_sh[q + j * d];
            conv_reduce(gv, w, am, an);
        }
    }
    __syncthreads();
    block_write_partial(am, an, ci, b, h, tile);
}

// ============================================================================
// Path B: large dilation (d = 512..8192), residue-walk with sliding window.
// grid.x = 128 * (2+2+4+4+8+8+16+16+32+32) = 15872, block = 256
// ============================================================================
__global__ void __launch_bounds__(256, 2)
residue_kernel(const float* __restrict__ X, const float* __restrict__ W,
               const int* __restrict__ idx) {
    int rem = blockIdx.x;
    int lci = 0;
#pragma unroll
    for (int c = 0; c < 10; c++) {
        int ddi = 9 + (c >> 1);
        int cnt = 128 * (1 << (ddi - 8));
        if (rem < cnt) { lci = c; break; }
        rem -= cnt;
    }
    int di = 9 + (lci >> 1), diff = lci & 1;
    int d = 1 << di;
    int nrb = 1 << (di - 8);
    int rb = rem % nrb;
    int h = (rem / nrb) % HH;
    int b = rem / (nrb * HH);
    int ci = 18 + lci;
    int tid = threadIdx.x;
    int r = rb * NTHREADS + tid;       // residue, < d
    int Te = TT - diff;
    int M = (Te - r + d - 1) / d;      // strip length >= 1

    int off[8];
    {
        const int* ip = idx + (ci * HH + h) * 8;
#pragma unroll
        for (int i = 0; i < 8; i++) off[i] = ip[i] * TT;
    }
    const float* Xb = X + b * CC * TT;

    float w[8][9];
    {
        const float* wp = W + (ci * 256 + h * 8) * 9;
#pragma unroll
        for (int k = 0; k < 8; k++)
#pragma unroll
            for (int j = 0; j < 9; j++) w[k][j] = __ldg(wp + k * 9 + j);
    }

    // init window for m = 0: strip indices -4..4
    float gv[9];
#pragma unroll
    for (int j = 0; j < 9; j++) {
        int s = j - 4;
        gv[j] = (s >= 0 && s < M) ? gsum(Xb, off, r + s * d, diff) : 0.f;
    }

    float am[8] = {0, 0, 0, 0, 0, 0, 0, 0};
    float an[8] = {0, 0, 0, 0, 0, 0, 0, 0};

#pragma unroll 1
    for (int m = 0; m < M; m++) {
        conv_reduce(gv, w, am, an);
        // slide window
#pragma unroll
        for (int j = 0; j < 8; j++) gv[j] = gv[j + 1];
        int s = m + 5;
        gv[8] = (s < M) ? gsum(Xb, off, r + s * d, diff) : 0.f;
    }
    block_write_partial(am, an, ci, b, h, rb);
}

// ============================================================================
// Deterministic final reduction -> d_out (writes every element)
// ============================================================================
__global__ void reduce_kernel(float* __restrict__ out) {
    int e = blockIdx.x * 256 + threadIdx.x;
    if (e >= BB * 14336) return;
    int b = e / 14336;
    int rem = e % 14336;
    int cig = rem / 512;
    int r2 = rem % 512;
    int which = r2 / 256;
    int hk = r2 % 256;
    int h = hk >> 3, k = hk & 7;
    int np;
    if (cig < NCOMBO_TILE) np = NTILE;
    else { int di = cig >> 1; np = 1 << (di - 8); }
    float s = 0.f;
    for (int p = 0; p < np; p++)
        s += g_partial[cig][b][h][p][which * 8 + k];
    out[e] = s;
}

extern "C" void kernel_launch(void* const* d_in, const int* in_sizes, int n_in,
                              void* d_out, int out_size) {
    const float* X = (const float*)d_in[0];
    const float* W = (const float*)d_in[1];
    const int* idx = (const int*)d_in[2];
    float* out = (float*)d_out;

    size_t smem = (size_t)(TILE + 8 * 256) * sizeof(float);   // 24576 B
    tile_kernel<<<NCOMBO_TILE * BB * HH * NTILE, NTHREADS, smem>>>(X, W, idx);
    residue_kernel<<<15872, NTHREADS>>>(X, W, idx);
    reduce_kernel<<<(BB * 14336 + 255) / 256, 256>>>(out);
}

// round 2
// speedup vs baseline: 1.6141x; 1.6141x over previous
#include <cuda_runtime.h>

#define BB 4
#define CC 17
#define TT 75000
#define HH 32
#define NTHREADS 256
#define TILE 4096
#define NTILE 19          // ceil(75000/4096)
#define MAXPART 32

// Deterministic partial accumulation scratch: [combo 28][b 4][h 32][part 32][16]
__device__ float g_partial[28][4][32][MAXPART][16];

// ---------------- f32x2 helpers ----------------
__device__ __forceinline__ unsigned long long pack2(float a, float b) {
    unsigned long long r;
    asm("mov.b64 %0, {%1, %2};" : "=l"(r) : "f"(a), "f"(b));
    return r;
}
__device__ __forceinline__ unsigned long long dup2(float a) {
    unsigned long long r;
    asm("mov.b64 %0, {%1, %1};" : "=l"(r) : "f"(a));
    return r;
}
__device__ __forceinline__ void mul2(unsigned long long& z, unsigned long long a,
                                     unsigned long long b) {
    asm("mul.rn.f32x2 %0, %1, %2;" : "=l"(z) : "l"(a), "l"(b));
}
__device__ __forceinline__ void fma2(unsigned long long& z, unsigned long long a,
                                     unsigned long long b) {
    asm("fma.rn.f32x2 %0, %1, %2, %0;" : "+l"(z) : "l"(a), "l"(b));
}
__device__ __forceinline__ void unpack2(unsigned long long z, float& lo, float& hi) {
    asm("mov.b64 {%0, %1}, %2;" : "=f"(lo), "=f"(hi) : "l"(z));
}

// ---------------- shared per-position conv + bucket reduce ----------------
// w2[kk][j] = { w[2kk][j], w[2kk+1][j] }
__device__ __forceinline__ void conv_reduce2(const float gv[9],
                                             const unsigned long long w2[4][9],
                                             float am[8], float an[8]) {
    unsigned long long acc[4];
    {
        unsigned long long g2 = dup2(gv[0]);
#pragma unroll
        for (int kk = 0; kk < 4; kk++) mul2(acc[kk], g2, w2[kk][0]);
    }
#pragma unroll
    for (int j = 1; j < 9; j++) {
        unsigned long long g2 = dup2(gv[j]);
#pragma unroll
        for (int kk = 0; kk < 4; kk++) fma2(acc[kk], g2, w2[kk][j]);
    }
    float z[8];
#pragma unroll
    for (int kk = 0; kk < 4; kk++) unpack2(acc[kk], z[2 * kk], z[2 * kk + 1]);

    float mx = fmaxf(fmaxf(fmaxf(z[0], z[1]), fmaxf(z[2], z[3])),
                     fmaxf(fmaxf(z[4], z[5]), fmaxf(z[6], z[7])));
    float mn = fminf(fminf(fminf(z[0], z[1]), fminf(z[2], z[3])),
                     fminf(fminf(z[4], z[5]), fminf(z[6], z[7])));
#pragma unroll
    for (int k = 0; k < 8; k++) {
        if (z[k] == mx) am[k] += z[k];
        if (z[k] == mn) an[k] += 1.0f;
    }
}

__device__ __forceinline__ void load_w2(const float* __restrict__ W, int ci, int h,
                                        unsigned long long w2[4][9]) {
    const float* wp = W + (ci * 256 + h * 8) * 9;
#pragma unroll
    for (int kk = 0; kk < 4; kk++)
#pragma unroll
        for (int j = 0; j < 9; j++)
            w2[kk][j] = pack2(__ldg(wp + (2 * kk) * 9 + j), __ldg(wp + (2 * kk + 1) * 9 + j));
}

__device__ __forceinline__ void block_write_partial(float* sw, float am[8], float an[8],
                                                    int ci, int b, int h, int blk) {
    int tid = threadIdx.x;
    int lane = tid & 31, warp = tid >> 5;
#pragma unroll
    for (int o = 0; o < 16; o++) {
        float v = (o < 8) ? am[o] : an[o - 8];
        v += __shfl_down_sync(0xffffffffu, v, 16);
        v += __shfl_down_sync(0xffffffffu, v, 8);
        v += __shfl_down_sync(0xffffffffu, v, 4);
        v += __shfl_down_sync(0xffffffffu, v, 2);
        v += __shfl_down_sync(0xffffffffu, v, 1);
        if (lane == 0) sw[warp * 16 + o] = v;
    }
    __syncthreads();
    if (tid < 16) {
        float s = 0.f;
#pragma unroll
        for (int wN = 0; wN < 8; wN++) s += sw[wN * 16 + tid];
        g_partial[ci][b][h][blk][tid] = s;
    }
}

// ============================================================================
// Path A: small dilation (di 0..8), templated on DI/DIFF, shared g tile.
// ============================================================================
template <int DI, int DIFF>
__device__ __forceinline__ void tile_body(int rlin, float* g_sh,
                                          const float* __restrict__ X,
                                          const float* __restrict__ W,
                                          const int* __restrict__ idx) {
    constexpr int D = 1 << DI;
    constexpr int HALO = 4 * D;
    constexpr int N = TILE + 2 * HALO;
    constexpr int CI = DI * 2 + DIFF;
    constexpr int Te = TT - DIFF;

    int tile = rlin % NTILE;
    int h = (rlin / NTILE) % HH;
    int b = rlin / (NTILE * HH);
    int t0 = tile * TILE;
    int tid = threadIdx.x;

    int off[8];
    {
        const int* ip = idx + (CI * HH + h) * 8;
#pragma unroll
        for (int i = 0; i < 8; i++) off[i] = ip[i] * TT;
    }
    const float* Xb = X + b * CC * TT;

    // ---- build g tile (zero padded outside [0, Te)) ----
    if (DIFF == 0) {
        for (int i = 2 * tid; i < N; i += 2 * NTHREADS) {
            int t = t0 - HALO + i;
            float v0 = 0.f, v1 = 0.f;
            if (t >= 0 && t + 1 < TT) {
#pragma unroll
                for (int c = 0; c < 8; c++) {
                    float2 x = __ldg((const float2*)(Xb + off[c] + t));
                    v0 += x.x; v1 += x.y;
                }
            } else {
                if (t >= 0 && t < TT) {
#pragma unroll
                    for (int c = 0; c < 8; c++) v0 += __ldg(Xb + off[c] + t);
                }
                if (t + 1 >= 0 && t + 1 < TT) {
#pragma unroll
                    for (int c = 0; c < 8; c++) v1 += __ldg(Xb + off[c] + t + 1);
                }
            }
            g_sh[i] = v0;
            g_sh[i + 1] = v1;
        }
    } else {
        for (int i = 2 * tid; i < N; i += 2 * NTHREADS) {
            int t = t0 - HALO + i;
            float s0 = 0.f, s1 = 0.f, s2 = 0.f;
            if (t >= 0 && t + 2 < TT) {
#pragma unroll
                for (int c = 0; c < 8; c++) {
                    float2 x = __ldg((const float2*)(Xb + off[c] + t));
                    s0 += x.x; s1 += x.y;
                    s2 += __ldg(Xb + off[c] + t + 2);
                }
            } else {
                if (t >= 0 && t < TT) {
#pragma unroll
                    for (int c = 0; c < 8; c++) s0 += __ldg(Xb + off[c] + t);
                }
                if (t + 1 >= 0 && t + 1 < TT) {
#pragma unroll
                    for (int c = 0; c < 8; c++) s1 += __ldg(Xb + off[c] + t + 1);
                }
                if (t + 2 >= 0 && t + 2 < TT) {
#pragma unroll
                    for (int c = 0; c < 8; c++) s2 += __ldg(Xb + off[c] + t + 2);
                }
            }
            g_sh[i] = (t >= 0 && t < Te) ? (s1 - s0) : 0.f;
            g_sh[i + 1] = (t + 1 >= 0 && t + 1 < Te) ? (s2 - s1) : 0.f;
        }
    }

    unsigned long long w2[4][9];
    load_w2(W, CI, h, w2);
    __syncthreads();

    float am[8] = {0, 0, 0, 0, 0, 0, 0, 0};
    float an[8] = {0, 0, 0, 0, 0, 0, 0, 0};

#pragma unroll 1
    for (int p = 0; p < TILE / NTHREADS; p++) {
        int q = tid + p * NTHREADS;
        int t = t0 + q;
        if (t < Te) {
            float gv[9];
#pragma unroll
            for (int j = 0; j < 9; j++) gv[j] = g_sh[q + j * D];  // imm offsets
            conv_reduce2(gv, w2, am, an);
        }
    }
    __syncthreads();
    block_write_partial(g_sh, am, an, CI, b, h, tile);
}

__global__ void __launch_bounds__(256, 2)
tile_all(const float* __restrict__ X, const float* __restrict__ W,
         const int* __restrict__ idx) {
    __shared__ float g_sh[TILE + 2 * 4 * 256];  // max N (DI=8): 6144 floats
    int ci = blockIdx.x / (NTILE * HH * BB);
    int r = blockIdx.x % (NTILE * HH * BB);
    switch (ci) {
        case 0:  tile_body<0, 0>(r, g_sh, X, W, idx); break;
        case 1:  tile_body<0, 1>(r, g_sh, X, W, idx); break;
        case 2:  tile_body<1, 0>(r, g_sh, X, W, idx); break;
        case 3:  tile_body<1, 1>(r, g_sh, X, W, idx); break;
        case 4:  tile_body<2, 0>(r, g_sh, X, W, idx); break;
        case 5:  tile_body<2, 1>(r, g_sh, X, W, idx); break;
        case 6:  tile_body<3, 0>(r, g_sh, X, W, idx); break;
        case 7:  tile_body<3, 1>(r, g_sh, X, W, idx); break;
        case 8:  tile_body<4, 0>(r, g_sh, X, W, idx); break;
        case 9:  tile_body<4, 1>(r, g_sh, X, W, idx); break;
        case 10: tile_body<5, 0>(r, g_sh, X, W, idx); break;
        case 11: tile_body<5, 1>(r, g_sh, X, W, idx); break;
        case 12: tile_body<6, 0>(r, g_sh, X, W, idx); break;
        case 13: tile_body<6, 1>(r, g_sh, X, W, idx); break;
        case 14: tile_body<7, 0>(r, g_sh, X, W, idx); break;
        case 15: tile_body<7, 1>(r, g_sh, X, W, idx); break;
        case 16: tile_body<8, 0>(r, g_sh, X, W, idx); break;
        case 17: tile_body<8, 1>(r, g_sh, X, W, idx); break;
    }
}

// ============================================================================
// Path B: large dilation (di 9..13), residue walk with sliding window.
// ============================================================================
template <int DIFF>
__device__ __forceinline__ float gsumT(const float* __restrict__ Xb,
                                       const int off[8], int t) {
    float s = 0.f;
#pragma unroll
    for (int i = 0; i < 8; i++) {
        const float* p = Xb + off[i] + t;
        float x = __ldg(p);
        if (DIFF) x = __ldg(p + 1) - x;
        s += x;
    }
    return s;
}

template <int DI, int DIFF>
__device__ __forceinline__ void residue_body(int rlin, float* sw,
                                             const float* __restrict__ X,
                                             const float* __restrict__ W,
                                             const int* __restrict__ idx) {
    constexpr int D = 1 << DI;
    constexpr int NRB = 1 << (DI - 8);
    constexpr int CI = 18 + (DI - 9) * 2 + DIFF;
    constexpr int Te = TT - DIFF;

    int rb = rlin % NRB;
    int h = (rlin / NRB) % HH;
    int b = rlin / (NRB * HH);
    int tid = threadIdx.x;
    int r = rb * NTHREADS + tid;            // residue < D
    int M = (Te - r + D - 1) / D;           // strip length >= 1

    int off[8];
    {
        const int* ip = idx + (CI * HH + h) * 8;
#pragma unroll
        for (int i = 0; i < 8; i++) off[i] = ip[i] * TT;
    }
    const float* Xb = X + b * CC * TT;

    unsigned long long w2[4][9];
    load_w2(W, CI, h, w2);

    float gv[9];
#pragma unroll
    for (int j = 0; j < 9; j++) {
        int s = j - 4;
        gv[j] = (s >= 0 && s < M) ? gsumT<DIFF>(Xb, off, r + s * D) : 0.f;
    }

    float am[8] = {0, 0, 0, 0, 0, 0, 0, 0};
    float an[8] = {0, 0, 0, 0, 0, 0, 0, 0};

#pragma unroll 1
    for (int m = 0; m < M; m++) {
        conv_reduce2(gv, w2, am, an);
#pragma unroll
        for (int j = 0; j < 8; j++) gv[j] = gv[j + 1];
        int s = m + 5;
        gv[8] = (s < M) ? gsumT<DIFF>(Xb, off, r + s * D) : 0.f;
    }
    __syncthreads();
    block_write_partial(sw, am, an, CI, b, h, rb);
}

__global__ void __launch_bounds__(256, 2)
residue_all(const float* __restrict__ X, const float* __restrict__ W,
            const int* __restrict__ idx) {
    __shared__ float sw[128];
    int bx = blockIdx.x;
    int lci, r;
    if      (bx < 256)   { lci = 0; r = bx; }
    else if (bx < 512)   { lci = 1; r = bx - 256; }
    else if (bx < 1024)  { lci = 2; r = bx - 512; }
    else if (bx < 1536)  { lci = 3; r = bx - 1024; }
    else if (bx < 2560)  { lci = 4; r = bx - 1536; }
    else if (bx < 3584)  { lci = 5; r = bx - 2560; }
    else if (bx < 5632)  { lci = 6; r = bx - 3584; }
    else if (bx < 7680)  { lci = 7; r = bx - 5632; }
    else if (bx < 11776) { lci = 8; r = bx - 7680; }
    else                 { lci = 9; r = bx - 11776; }
    switch (lci) {
        case 0: residue_body<9, 0>(r, sw, X, W, idx); break;
        case 1: residue_body<9, 1>(r, sw, X, W, idx); break;
        case 2: residue_body<10, 0>(r, sw, X, W, idx); break;
        case 3: residue_body<10, 1>(r, sw, X, W, idx); break;
        case 4: residue_body<11, 0>(r, sw, X, W, idx); break;
        case 5: residue_body<11, 1>(r, sw, X, W, idx); break;
        case 6: residue_body<12, 0>(r, sw, X, W, idx); break;
        case 7: residue_body<12, 1>(r, sw, X, W, idx); break;
        case 8: residue_body<13, 0>(r, sw, X, W, idx); break;
        case 9: residue_body<13, 1>(r, sw, X, W, idx); break;
    }
}

// ============================================================================
// Deterministic final reduction -> d_out (writes every element)
// ============================================================================
__global__ void reduce_kernel(float* __restrict__ out) {
    int e = blockIdx.x * 256 + threadIdx.x;
    if (e >= BB * 14336) return;
    int b = e / 14336;
    int rem = e % 14336;
    int cig = rem / 512;
    int r2 = rem % 512;
    int which = r2 / 256;
    int hk = r2 % 256;
    int h = hk >> 3, k = hk & 7;
    int np;
    if (cig < 18) np = NTILE;
    else { int di = cig >> 1; np = 1 << (di - 8); }
    float s = 0.f;
    for (int p = 0; p < np; p++)
        s += g_partial[cig][b][h][p][which * 8 + k];
    out[e] = s;
}

extern "C" void kernel_launch(void* const* d_in, const int* in_sizes, int n_in,
                              void* d_out, int out_size) {
    const float* X = (const float*)d_in[0];
    const float* W = (const float*)d_in[1];
    const int* idx = (const int*)d_in[2];
    float* out = (float*)d_out;

    tile_all<<<18 * NTILE * HH * BB, NTHREADS>>>(X, W, idx);
    residue_all<<<15872, NTHREADS>>>(X, W, idx);
    reduce_kernel<<<(BB * 14336 + 255) / 256, 256>>>(out);
}